// round 12
// baseline (speedup 1.0000x reference)
#include <cuda_runtime.h>
#include <cuda_bf16.h>

// Scratch (no cudaMalloc allowed). Shapes: B=1024 (<=4096), E=50000 (<=65536).
__device__ float g_hr[4096];      // hr_part[b] + bias
__device__ float g_tail[65536];   // tail_part[e]

#define THREADS 256
#define BTILE   16   // b-rows per bcast CTA (measured plateau optimum)

// ---------------------------------------------------------------------------
// dots kernel v2 (C==512 fast path): single balanced wave.
//  - grid = SMs x resident CTAs (host-computed) -> no wave quantization
//  - each warp owns a CONTIGUOUS slice of tail rows; W2 held in registers
//  - first B warps additionally compute one hr row each (W1 + bias)
//  - zero-fills trailing [zstart, total) of output
// ---------------------------------------------------------------------------
__global__ __launch_bounds__(THREADS)
void dots512_kernel(const float* __restrict__ hr,
                    const float* __restrict__ tail,
                    const float* __restrict__ W,   // [1024]: W1 | W2
                    const float* __restrict__ bias,
                    int B, int E,
                    float* __restrict__ out,
                    long long zstart, long long total,
                    int nblocks) {
    const int tid   = threadIdx.x;
    const int gid   = blockIdx.x * THREADS + tid;
    const int gsz   = nblocks * THREADS;
    const int lane  = tid & 31;
    const int gwarp = gid >> 5;
    const int nwarps = gsz >> 5;

    // Trailing zero-fill (reference returns (scores, 0)).
    for (long long zi = zstart + gid; zi < total; zi += gsz)
        out[zi] = 0.0f;

    // ---- hr rows: warp w < B handles hr row w with W1. ----
    if (gwarp < B) {
        const float4* r4 = reinterpret_cast<const float4*>(hr + (size_t)gwarp * 512);
        const float4* w4 = reinterpret_cast<const float4*>(W);
        float4 a0 = __ldg(r4 + lane);
        float4 a1 = __ldg(r4 + lane + 32);
        float4 a2 = __ldg(r4 + lane + 64);
        float4 a3 = __ldg(r4 + lane + 96);
        float4 b0 = __ldg(w4 + lane);
        float4 b1 = __ldg(w4 + lane + 32);
        float4 b2 = __ldg(w4 + lane + 64);
        float4 b3 = __ldg(w4 + lane + 96);
        float s0 = a0.x * b0.x + a0.y * b0.y + a0.z * b0.z + a0.w * b0.w;
        float s1 = a1.x * b1.x + a1.y * b1.y + a1.z * b1.z + a1.w * b1.w;
        float s2 = a2.x * b2.x + a2.y * b2.y + a2.z * b2.z + a2.w * b2.w;
        float s3 = a3.x * b3.x + a3.y * b3.y + a3.z * b3.z + a3.w * b3.w;
        float acc = (s0 + s1) + (s2 + s3);
#pragma unroll
        for (int off = 16; off; off >>= 1)
            acc += __shfl_xor_sync(0xffffffffu, acc, off);
        if (lane == 0) g_hr[gwarp] = acc + bias[0];
    }

    // ---- tail rows: contiguous balanced partition, W2 in registers. ----
    int base = E / nwarps;
    int rem  = E - base * nwarps;
    int r_begin = gwarp * base + (gwarp < rem ? gwarp : rem);
    int r_end   = r_begin + base + (gwarp < rem ? 1 : 0);

    const float4* w4 = reinterpret_cast<const float4*>(W + 512);
    float4 b0 = __ldg(w4 + lane);
    float4 b1 = __ldg(w4 + lane + 32);
    float4 b2 = __ldg(w4 + lane + 64);
    float4 b3 = __ldg(w4 + lane + 96);

    for (int r = r_begin; r < r_end; ++r) {
        const float4* r4 = reinterpret_cast<const float4*>(tail + (size_t)r * 512);
        float4 a0 = __ldg(r4 + lane);
        float4 a1 = __ldg(r4 + lane + 32);
        float4 a2 = __ldg(r4 + lane + 64);
        float4 a3 = __ldg(r4 + lane + 96);
        float s0 = a0.x * b0.x + a0.y * b0.y + a0.z * b0.z + a0.w * b0.w;
        float s1 = a1.x * b1.x + a1.y * b1.y + a1.z * b1.z + a1.w * b1.w;
        float s2 = a2.x * b2.x + a2.y * b2.y + a2.z * b2.z + a2.w * b2.w;
        float s3 = a3.x * b3.x + a3.y * b3.y + a3.z * b3.z + a3.w * b3.w;
        float acc = (s0 + s1) + (s2 + s3);
#pragma unroll
        for (int off = 16; off; off >>= 1)
            acc += __shfl_xor_sync(0xffffffffu, acc, off);
        if (lane == 0) g_tail[r] = acc;
    }
}

// ---------------------------------------------------------------------------
// Generic dots fallback (any C): warp per row over B+E rows.
// ---------------------------------------------------------------------------
__global__ void dots_kernel(const float* __restrict__ hr,
                            const float* __restrict__ tail,
                            const float* __restrict__ W,
                            const float* __restrict__ bias,
                            int B, int E, int C,
                            float* __restrict__ out,
                            long long zstart, long long total) {
    int gid  = blockIdx.x * blockDim.x + threadIdx.x;
    int warp = gid >> 5;
    int lane = threadIdx.x & 31;
    long long zi = zstart + (long long)gid;
    if (zi < total) out[zi] = 0.0f;
    if (warp >= B + E) return;
    const float* row; const float* w;
    if (warp < B) { row = hr   + (size_t)warp * C;       w = W;     }
    else          { row = tail + (size_t)(warp - B) * C; w = W + C; }
    float acc = 0.0f;
    for (int k = lane; k < C; k += 32)
        acc += __ldg(row + k) * __ldg(w + k);
#pragma unroll
    for (int off = 16; off; off >>= 1)
        acc += __shfl_xor_sync(0xffffffffu, acc, off);
    if (lane == 0) {
        if (warp < B) g_hr[warp] = acc + bias[0];
        else          g_tail[warp - B] = acc;
    }
}

// ---------------------------------------------------------------------------
// Broadcast write, b-tiled (frozen R10 config: 31.1us = LTS wall).
// ---------------------------------------------------------------------------
__global__ __launch_bounds__(THREADS)
void bcast_vec_kernel(float* __restrict__ out, int E4, long long E, int B) {
    __shared__ float sh[BTILE];
    int b0 = blockIdx.y * BTILE;
    if (threadIdx.x < BTILE) {
        int b = b0 + threadIdx.x;
        sh[threadIdx.x] = (b < B) ? g_hr[b] : 0.0f;
    }
    __syncthreads();

    int e4 = blockIdx.x * blockDim.x + threadIdx.x;
    if (e4 >= E4) return;

    float4 t = __ldg(reinterpret_cast<const float4*>(g_tail) + e4);

    float4* base = reinterpret_cast<float4*>(out + (size_t)b0 * E) + e4;
    long long rowstride4 = E >> 2;

    int nb = B - b0;
    if (nb >= BTILE) {
#pragma unroll
        for (int i = 0; i < BTILE; i++) {
            float h = sh[i];
            float4 r = make_float4(t.x + h, t.y + h, t.z + h, t.w + h);
            __stcs(base + (long long)i * rowstride4, r);
        }
    } else {
        for (int i = 0; i < nb; i++) {
            float h = sh[i];
            float4 r = make_float4(t.x + h, t.y + h, t.z + h, t.w + h);
            __stcs(base + (long long)i * rowstride4, r);
        }
    }
}

// Scalar fallback for E % 4 != 0.
__global__ void bcast_scalar_kernel(float* __restrict__ out, int E) {
    int e = blockIdx.x * blockDim.x + threadIdx.x;
    if (e >= E) return;
    int b = blockIdx.y;
    out[(size_t)b * E + e] = g_hr[b] + g_tail[e];
}

extern "C" void kernel_launch(void* const* d_in, const int* in_sizes, int n_in,
                              void* d_out, int out_size) {
    const float* hr   = (const float*)d_in[0];  // [B, C]
    const float* tail = (const float*)d_in[1];  // [E, C]
    const float* W    = (const float*)d_in[2];  // [1, 2C]
    const float* bias = (const float*)d_in[3];  // [1]
    float* out = (float*)d_out;

    int C = in_sizes[2] / 2;
    int B = in_sizes[0] / C;
    int E = in_sizes[1] / C;

    long long BE    = (long long)B * (long long)E;
    long long total = (long long)out_size;

    // 1) dots
    if (C == 512 && B <= 4096 && E <= 65536) {
        int sm_count = 0;
        cudaDeviceGetAttribute(&sm_count, cudaDevAttrMultiProcessorCount, 0);
        if (sm_count <= 0) sm_count = 148;
        int max_blk = 0;
        cudaOccupancyMaxActiveBlocksPerMultiprocessor(
            &max_blk, dots512_kernel, THREADS, 0);
        if (max_blk <= 0) max_blk = 4;
        int nblocks = sm_count * max_blk;
        // Need at least B warps for the hr path.
        int min_blocks = (B * 32 + THREADS - 1) / THREADS;
        if (nblocks < min_blocks) nblocks = min_blocks;
        dots512_kernel<<<nblocks, THREADS>>>(hr, tail, W, bias, B, E,
                                             out, BE, total, nblocks);
    } else {
        int rows = B + E;
        long long lanes = (long long)rows * 32;
        long long extra = (total > BE) ? (total - BE) : 0;
        if (extra > lanes) lanes = extra;
        int blocks = (int)((lanes + THREADS - 1) / THREADS);
        dots_kernel<<<blocks, THREADS>>>(hr, tail, W, bias, B, E, C,
                                         out, BE, total);
    }

    // 2) broadcast sum -> out
    if ((E & 3) == 0) {
        int E4 = E >> 2;
        dim3 grid((E4 + THREADS - 1) / THREADS, (B + BTILE - 1) / BTILE);
        bcast_vec_kernel<<<grid, THREADS>>>(out, E4, (long long)E, B);
    } else {
        dim3 grid((E + THREADS - 1) / THREADS, B);
        bcast_scalar_kernel<<<grid, THREADS>>>(out, E);
    }
}

// round 13
// speedup vs baseline: 1.0300x; 1.0300x over previous
#include <cuda_runtime.h>
#include <cuda_bf16.h>

// Scratch (no cudaMalloc allowed). Shapes: B=1024 (<=4096), E=50000 (<=65536).
__device__ float g_hr[4096];      // hr_part[b] + bias
__device__ float g_tail[65536];   // tail_part[e]

#define THREADS 256
#define BTILE   16   // b-rows per bcast CTA (measured plateau optimum)

// ---------------------------------------------------------------------------
// Dots kernel (R10 config = best measured): warp per row over B+E rows,
// C==512 fast path batches all 8 LDG.128s. Zero-fills trailing output.
// Ends with PDL trigger so the bcast grid may begin dispatch.
// ---------------------------------------------------------------------------
__global__ void dots_kernel(const float* __restrict__ hr,
                            const float* __restrict__ tail,
                            const float* __restrict__ W,   // [2C]: W1 | W2
                            const float* __restrict__ bias,
                            int B, int E, int C,
                            float* __restrict__ out,
                            long long zstart, long long total) {
    int gid  = blockIdx.x * blockDim.x + threadIdx.x;
    int warp = gid >> 5;
    int lane = threadIdx.x & 31;

    long long zi = zstart + (long long)gid;
    if (zi < total) out[zi] = 0.0f;

    int rows = B + E;
    if (warp < rows) {
        const float* row;
        const float* w;
        if (warp < B) { row = hr   + (size_t)warp * C;       w = W;     }
        else          { row = tail + (size_t)(warp - B) * C; w = W + C; }

        float acc = 0.0f;
        if (C == 512) {
            const float4* r4 = reinterpret_cast<const float4*>(row);
            const float4* w4 = reinterpret_cast<const float4*>(w);
            float4 a0 = __ldg(r4 + lane);
            float4 a1 = __ldg(r4 + lane + 32);
            float4 a2 = __ldg(r4 + lane + 64);
            float4 a3 = __ldg(r4 + lane + 96);
            float4 b0 = __ldg(w4 + lane);
            float4 b1 = __ldg(w4 + lane + 32);
            float4 b2 = __ldg(w4 + lane + 64);
            float4 b3 = __ldg(w4 + lane + 96);
            float s0 = a0.x * b0.x + a0.y * b0.y + a0.z * b0.z + a0.w * b0.w;
            float s1 = a1.x * b1.x + a1.y * b1.y + a1.z * b1.z + a1.w * b1.w;
            float s2 = a2.x * b2.x + a2.y * b2.y + a2.z * b2.z + a2.w * b2.w;
            float s3 = a3.x * b3.x + a3.y * b3.y + a3.z * b3.z + a3.w * b3.w;
            acc = (s0 + s1) + (s2 + s3);
        } else if ((C & 3) == 0) {
            const float4* r4 = reinterpret_cast<const float4*>(row);
            const float4* w4 = reinterpret_cast<const float4*>(w);
            int C4 = C >> 2;
            for (int k = lane; k < C4; k += 32) {
                float4 a = __ldg(r4 + k);
                float4 b = __ldg(w4 + k);
                acc += a.x * b.x + a.y * b.y + a.z * b.z + a.w * b.w;
            }
        } else {
            for (int k = lane; k < C; k += 32)
                acc += __ldg(row + k) * __ldg(w + k);
        }
#pragma unroll
        for (int off = 16; off; off >>= 1)
            acc += __shfl_xor_sync(0xffffffffu, acc, off);

        if (lane == 0) {
            if (warp < B) g_hr[warp] = acc + bias[0];
            else          g_tail[warp - B] = acc;
        }
    }

    // PDL: scratch writes above are complete for this thread.
    cudaTriggerProgrammaticLaunchCompletion();
}

// ---------------------------------------------------------------------------
// Broadcast write, b-tiled (frozen: 31.1us = LTS wall). PDL-aware: prologue
// (index math) runs while dots drains; gridDependencySynchronize before
// touching g_hr / g_tail.
// ---------------------------------------------------------------------------
__global__ __launch_bounds__(THREADS)
void bcast_vec_kernel(float* __restrict__ out, int E4, long long E, int B) {
    // --- pre-sync prologue: no dependence on primary kernel ---
    __shared__ float sh[BTILE];
    int b0 = blockIdx.y * BTILE;
    int e4 = blockIdx.x * blockDim.x + threadIdx.x;
    float4* base = reinterpret_cast<float4*>(out + (size_t)b0 * E) + e4;
    long long rowstride4 = E >> 2;
    int nb = B - b0;

    // --- wait for dots results ---
    cudaGridDependencySynchronize();

    if (threadIdx.x < BTILE) {
        int b = b0 + threadIdx.x;
        sh[threadIdx.x] = (b < B) ? g_hr[b] : 0.0f;
    }
    __syncthreads();

    if (e4 >= E4) return;

    float4 t = __ldg(reinterpret_cast<const float4*>(g_tail) + e4);

    if (nb >= BTILE) {
#pragma unroll
        for (int i = 0; i < BTILE; i++) {
            float h = sh[i];
            float4 r = make_float4(t.x + h, t.y + h, t.z + h, t.w + h);
            __stcs(base + (long long)i * rowstride4, r);
        }
    } else {
        for (int i = 0; i < nb; i++) {
            float h = sh[i];
            float4 r = make_float4(t.x + h, t.y + h, t.z + h, t.w + h);
            __stcs(base + (long long)i * rowstride4, r);
        }
    }
}

// Scalar fallback for E % 4 != 0 (plain launch, no PDL).
__global__ void bcast_scalar_kernel(float* __restrict__ out, int E) {
    int e = blockIdx.x * blockDim.x + threadIdx.x;
    if (e >= E) return;
    int b = blockIdx.y;
    out[(size_t)b * E + e] = g_hr[b] + g_tail[e];
}

extern "C" void kernel_launch(void* const* d_in, const int* in_sizes, int n_in,
                              void* d_out, int out_size) {
    const float* hr   = (const float*)d_in[0];  // [B, C]
    const float* tail = (const float*)d_in[1];  // [E, C]
    const float* W    = (const float*)d_in[2];  // [1, 2C]
    const float* bias = (const float*)d_in[3];  // [1]
    float* out = (float*)d_out;

    int C = in_sizes[2] / 2;
    int B = in_sizes[0] / C;
    int E = in_sizes[1] / C;

    long long BE    = (long long)B * (long long)E;
    long long total = (long long)out_size;

    // 1) dots (+ trailing zero-fill)
    {
        int rows = B + E;
        long long lanes = (long long)rows * 32;
        long long extra = (total > BE) ? (total - BE) : 0;
        if (extra > lanes) lanes = extra;
        int blocks = (int)((lanes + THREADS - 1) / THREADS);
        dots_kernel<<<blocks, THREADS>>>(hr, tail, W, bias, B, E, C,
                                         out, BE, total);
    }

    // 2) broadcast sum -> out (PDL: overlap dispatch with dots drain)
    if ((E & 3) == 0) {
        int E4 = E >> 2;
        dim3 grid((E4 + THREADS - 1) / THREADS, (B + BTILE - 1) / BTILE);

        cudaLaunchConfig_t cfg = {};
        cfg.gridDim  = grid;
        cfg.blockDim = dim3(THREADS, 1, 1);
        cfg.dynamicSmemBytes = 0;
        cudaLaunchAttribute attrs[1];
        attrs[0].id = cudaLaunchAttributeProgrammaticStreamSerialization;
        attrs[0].val.programmaticStreamSerializationAllowed = 1;
        cfg.attrs = attrs;
        cfg.numAttrs = 1;

        cudaLaunchKernelEx(&cfg, bcast_vec_kernel,
                           out, E4, (long long)E, B);
    } else {
        dim3 grid((E + THREADS - 1) / THREADS, B);
        bcast_scalar_kernel<<<grid, THREADS>>>(out, E);
    }
}